// round 1
// baseline (speedup 1.0000x reference)
#include <cuda_runtime.h>
#include <cstdint>

// DigitCaps dynamic routing, fused.
// Math: b_t[i,j] = u_hat[b,i,j,:] . Vsum_t[b,j,:]  where Vsum_t = sum_{tau<t} v_tau
// => no per-(i,j) logit state; each iteration is one sweep recomputing u_hat.

#define B_      512
#define NI      1152
#define NJ      10
#define DI      8
#define DO      16

#define THREADS 512
#define BP      8        // batch-pairs per block (B_REG = 2)
#define BT      16       // batches per block
#define G_      6        // i-groups per block
#define ISPLITS 8
#define ICHUNK  144      // NI / ISPLITS
#define NCHUNK  24       // ICHUNK / G_
#define NPART   (ISPLITS * G_)   // 48 partials per batch

#define WROW    132              // 128 + 4 pad (bank-conflict break)
#define WTILE   (NJ * WROW)      // 1320 words per i
#define WBUF    (G_ * WTILE)     // 7920 words per buffer
#define VROW    18               // padded Vsum row
#define SMEM_WORDS (2 * WBUF + BT * NJ * VROW)   // 15840 + 2880 = 18720 -> 74880 B

__device__ float g_partial[(size_t)B_ * NPART * NJ * DO];  // 15.7 MB scratch
__device__ float g_vsum[B_ * NJ * DO];

using ull = unsigned long long;

__device__ __forceinline__ ull fma2(ull a, ull b, ull c) {
    ull d; asm("fma.rn.f32x2 %0, %1, %2, %3;" : "=l"(d) : "l"(a), "l"(b), "l"(c)); return d;
}
__device__ __forceinline__ ull add2(ull a, ull b) {
    ull d; asm("add.rn.f32x2 %0, %1, %2;" : "=l"(d) : "l"(a), "l"(b)); return d;
}
__device__ __forceinline__ ull mul2(ull a, ull b) {
    ull d; asm("mul.rn.f32x2 %0, %1, %2;" : "=l"(d) : "l"(a), "l"(b)); return d;
}
__device__ __forceinline__ ull bcast2(float x) {
    ull d; asm("mov.b64 %0, {%1, %1};" : "=l"(d) : "f"(x)); return d;
}
__device__ __forceinline__ ull pack2(float x, float y) {
    ull d; asm("mov.b64 %0, {%1, %2};" : "=l"(d) : "f"(x), "f"(y)); return d;
}
__device__ __forceinline__ float sum2(ull a) {
    float l, h; asm("mov.b64 {%0, %1}, %2;" : "=f"(l), "=f"(h) : "l"(a)); return l + h;
}
__device__ __forceinline__ void cpa16(uint32_t dst, const void* src) {
    asm volatile("cp.async.cg.shared.global [%0], [%1], 16;" :: "r"(dst), "l"(src));
}

__device__ __forceinline__ void load_chunk(uint32_t sbase, const float* __restrict__ W,
                                           int i_first, int buf, int tid) {
    const float* src0 = W + (size_t)i_first * (NJ * DI * DO);
    uint32_t d0 = sbase + (uint32_t)buf * (WBUF * 4);
    // 6 i's * 10 j * 32 quads of 16B = 1920 copies
    #pragma unroll 1
    for (int cidx = tid; cidx < G_ * NJ * 32; cidx += THREADS) {
        int q  = cidx & 31;
        int r  = cidx >> 5;           // 0..59
        int jj = r % NJ;
        int gg = r / NJ;
        const float* src = src0 + gg * (NJ * DI * DO) + jj * (DI * DO) + q * 4;
        uint32_t dst = d0 + (uint32_t)(gg * WTILE + jj * WROW + q * 4) * 4;
        cpa16(dst, src);
    }
    asm volatile("cp.async.commit_group;");
}

template <bool FIRST>
__global__ void __launch_bounds__(THREADS, 1)
sweep_kernel(const float* __restrict__ u, const float* __restrict__ W) {
    extern __shared__ float smem[];
    float* wst = smem;                  // W stage, double buffered
    float* vsm = smem + 2 * WBUF;       // Vsum stage (padded rows)

    const int tid  = threadIdx.x;
    const int warp = tid >> 5;
    const int lane = tid & 31;
    const int seg  = lane / 10;         // 0..2 active, 3 idle
    const bool active = (seg < 3);
    const int j    = lane - seg * 10;
    const int unit = warp * 3 + (active ? seg : 0);
    const int bp   = unit & 7;
    const int g    = unit >> 3;         // 0..5

    const int i0    = blockIdx.x * ICHUNK;
    const int bbase = blockIdx.y * BT;

    if (!FIRST) {
        for (int idx = tid; idx < BT * NJ * DO; idx += THREADS) {
            vsm[(idx >> 4) * VROW + (idx & 15)] = g_vsum[bbase * NJ * DO + idx];
        }
    }

    uint32_t smem_base = (uint32_t)__cvta_generic_to_shared(wst);

    load_chunk(smem_base, W, i0, 0, tid);

    ull sacc0[8], sacc1[8];
    #pragma unroll
    for (int k = 0; k < 8; k++) { sacc0[k] = 0ULL; sacc1[k] = 0ULL; }

    const int b0 = bbase + bp * 2;
    const float* u0p = u + (size_t)b0 * NI * DI;
    const float* u1p = u0p + (size_t)NI * DI;
    const float* vs0 = vsm + (bp * 2 * NJ + j) * VROW;
    const float* vs1 = vs0 + NJ * VROW;

    for (int c = 0; c < NCHUNK; c++) {
        const int buf = c & 1;
        if (c + 1 < NCHUNK) {
            load_chunk(smem_base, W, i0 + (c + 1) * G_, buf ^ 1, tid);
            asm volatile("cp.async.wait_group 1;");
        } else {
            asm volatile("cp.async.wait_group 0;");
        }
        __syncthreads();

        if (active) {
            const int i = i0 + c * G_ + g;
            float4 ua = *(const float4*)(u0p + (size_t)i * DI);
            float4 ub = *(const float4*)(u0p + (size_t)i * DI + 4);
            float4 uc = *(const float4*)(u1p + (size_t)i * DI);
            float4 ud = *(const float4*)(u1p + (size_t)i * DI + 4);
            float ur0[8] = {ua.x, ua.y, ua.z, ua.w, ub.x, ub.y, ub.z, ub.w};
            float ur1[8] = {uc.x, uc.y, uc.z, uc.w, ud.x, ud.y, ud.z, ud.w};

            const float* wt = wst + buf * WBUF + g * WTILE + j * WROW;
            ull a0[8], a1[8];
            #pragma unroll
            for (int k = 0; k < 8; k++) { a0[k] = 0ULL; a1[k] = 0ULL; }

            #pragma unroll
            for (int e = 0; e < 8; e++) {
                float4 w0 = *(const float4*)(wt + e * 16);
                float4 w1 = *(const float4*)(wt + e * 16 + 4);
                float4 w2 = *(const float4*)(wt + e * 16 + 8);
                float4 w3 = *(const float4*)(wt + e * 16 + 12);
                ull wv[8];
                wv[0] = pack2(w0.x, w0.y); wv[1] = pack2(w0.z, w0.w);
                wv[2] = pack2(w1.x, w1.y); wv[3] = pack2(w1.z, w1.w);
                wv[4] = pack2(w2.x, w2.y); wv[5] = pack2(w2.z, w2.w);
                wv[6] = pack2(w3.x, w3.y); wv[7] = pack2(w3.z, w3.w);
                ull ue0 = bcast2(ur0[e]);
                ull ue1 = bcast2(ur1[e]);
                #pragma unroll
                for (int k = 0; k < 8; k++) {
                    a0[k] = fma2(ue0, wv[k], a0[k]);
                    a1[k] = fma2(ue1, wv[k], a1[k]);
                }
            }

            if (FIRST) {
                // c is uniform softmax(0) = 0.1; fold the 0.1 at the store.
                #pragma unroll
                for (int k = 0; k < 8; k++) {
                    sacc0[k] = add2(sacc0[k], a0[k]);
                    sacc1[k] = add2(sacc1[k], a1[k]);
                }
            } else {
                ull d0 = 0ULL, d1 = 0ULL;
                #pragma unroll
                for (int k = 0; k < 8; k++) {
                    ull v0 = ((const ull*)vs0)[k];
                    ull v1 = ((const ull*)vs1)[k];
                    d0 = fma2(a0[k], v0, d0);
                    d1 = fma2(a1[k], v1, d1);
                }
                float l0 = sum2(d0), l1 = sum2(d1);
                float e0 = __expf(l0), e1 = __expf(l1);
                float t0 = 0.f, t1 = 0.f;
                const int base = seg * 10;
                #pragma unroll
                for (int jj = 0; jj < 10; jj++) {
                    t0 += __shfl_sync(0x3FFFFFFFu, e0, base + jj);
                    t1 += __shfl_sync(0x3FFFFFFFu, e1, base + jj);
                }
                ull c0 = bcast2(e0 / t0);
                ull c1 = bcast2(e1 / t1);
                #pragma unroll
                for (int k = 0; k < 8; k++) {
                    sacc0[k] = fma2(c0, a0[k], sacc0[k]);
                    sacc1[k] = fma2(c1, a1[k], sacc1[k]);
                }
            }
        }
        __syncthreads();
    }

    if (active) {
        const int p = blockIdx.x * G_ + g;
        ull* dst0 = (ull*)(g_partial + (((size_t)b0 * NPART + p) * NJ + j) * DO);
        ull* dst1 = dst0 + (size_t)NPART * NJ * DO / 2;
        if (FIRST) {
            ull tenth = bcast2(0.1f);
            #pragma unroll
            for (int k = 0; k < 8; k++) {
                dst0[k] = mul2(sacc0[k], tenth);
                dst1[k] = mul2(sacc1[k], tenth);
            }
        } else {
            #pragma unroll
            for (int k = 0; k < 8; k++) {
                dst0[k] = sacc0[k];
                dst1[k] = sacc1[k];
            }
        }
    }
}

template <bool FIRST, bool LAST>
__global__ void reduce_kernel(float* __restrict__ out) {
    int t = blockIdx.x * blockDim.x + threadIdx.x;
    if (t >= B_ * NJ) return;
    int b = t / NJ;
    int j = t - b * NJ;

    float acc[16];
    #pragma unroll
    for (int d = 0; d < 16; d++) acc[d] = 0.f;

    const float* src = g_partial + (((size_t)b * NPART) * NJ + j) * DO;
    #pragma unroll 4
    for (int p = 0; p < NPART; p++) {
        const float4* s4 = (const float4*)(src + (size_t)p * NJ * DO);
        float4 x0 = s4[0], x1 = s4[1], x2 = s4[2], x3 = s4[3];
        acc[0]  += x0.x; acc[1]  += x0.y; acc[2]  += x0.z; acc[3]  += x0.w;
        acc[4]  += x1.x; acc[5]  += x1.y; acc[6]  += x1.z; acc[7]  += x1.w;
        acc[8]  += x2.x; acc[9]  += x2.y; acc[10] += x2.z; acc[11] += x2.w;
        acc[12] += x3.x; acc[13] += x3.y; acc[14] += x3.z; acc[15] += x3.w;
    }

    float sq = 0.f;
    #pragma unroll
    for (int d = 0; d < 16; d++) sq += acc[d] * acc[d];
    float norm = sqrtf(sq);
    float factor = sq / (norm * (1.f + sq));

    if (LAST) {
        float* o = out + (size_t)(b * NJ + j) * DO;
        #pragma unroll
        for (int d = 0; d < 16; d++) o[d] = factor * acc[d];
    } else {
        float* vp = g_vsum + (b * NJ + j) * DO;
        if (FIRST) {
            #pragma unroll
            for (int d = 0; d < 16; d++) vp[d] = factor * acc[d];
        } else {
            #pragma unroll
            for (int d = 0; d < 16; d++) vp[d] += factor * acc[d];
        }
    }
}

extern "C" void kernel_launch(void* const* d_in, const int* in_sizes, int n_in,
                              void* d_out, int out_size) {
    const float* u = (const float*)d_in[0];
    const float* W = (const float*)d_in[1];
    float* out = (float*)d_out;

    const int smem = SMEM_WORDS * 4;  // 74880 B
    cudaFuncSetAttribute(sweep_kernel<true>,  cudaFuncAttributeMaxDynamicSharedMemorySize, smem);
    cudaFuncSetAttribute(sweep_kernel<false>, cudaFuncAttributeMaxDynamicSharedMemorySize, smem);

    dim3 grid(ISPLITS, B_ / BT);
    const int rblocks = (B_ * NJ + 255) / 256;

    // Iteration 1: c uniform (softmax of zeros)
    sweep_kernel<true><<<grid, THREADS, smem>>>(u, W);
    reduce_kernel<true, false><<<rblocks, 256>>>(out);
    // Iteration 2: logits = u_hat . v1
    sweep_kernel<false><<<grid, THREADS, smem>>>(u, W);
    reduce_kernel<false, false><<<rblocks, 256>>>(out);
    // Iteration 3: logits = u_hat . (v1 + v2); emit v3
    sweep_kernel<false><<<grid, THREADS, smem>>>(u, W);
    reduce_kernel<false, true><<<rblocks, 256>>>(out);
}

// round 2
// speedup vs baseline: 1.2675x; 1.2675x over previous
#include <cuda_runtime.h>
#include <cstdint>

// DigitCaps dynamic routing, fused.
// b_t[i,j] = u_hat[b,i,j,:] . Vsum_t[b,j,:], Vsum_t = sum_{tau<t} v_tau
// => no per-(i,j) logit state; each iteration is one sweep recomputing u_hat.

#define B_      512
#define NI      1152
#define NJ      10
#define DI      8
#define DO      16

#define THREADS 512
#define BT      16       // batches per block (8 pairs)
#define G_      6        // i-groups per block
#define ISPLITS 8
#define ICHUNK  144      // NI / ISPLITS
#define NCHUNK  24       // ICHUNK / G_
#define NPART   ISPLITS  // 8 partials per (b,j) after in-block g-reduction

#define WROW    132              // 128 + 4 pad
#define WTILE   (NJ * WROW)      // 1320 words per i
#define WBUF    (G_ * WTILE)     // 7920 words per buffer
#define NBUF    3
#define VROW    18
#define SMEM_WORDS (NBUF * WBUF + BT * NJ * VROW)   // 23760 + 2880 = 26640 (106560 B)

__device__ float g_partial[(size_t)B_ * NPART * NJ * DO];  // 2.6 MB
__device__ float g_vsum[B_ * NJ * DO];

using ull = unsigned long long;

__device__ __forceinline__ ull fma2(ull a, ull b, ull c) {
    ull d; asm("fma.rn.f32x2 %0, %1, %2, %3;" : "=l"(d) : "l"(a), "l"(b), "l"(c)); return d;
}
__device__ __forceinline__ ull bcast2(float x) {
    ull d; asm("mov.b64 %0, {%1, %1};" : "=l"(d) : "f"(x)); return d;
}
__device__ __forceinline__ float sum2(ull a) {
    float l, h; asm("mov.b64 {%0, %1}, %2;" : "=f"(l), "=f"(h) : "l"(a)); return l + h;
}
__device__ __forceinline__ void st2(float* p, ull v) {
    *(ull*)p = v;
}
__device__ __forceinline__ void cpa16(uint32_t dst, const void* src) {
    asm volatile("cp.async.cg.shared.global [%0], [%1], 16;" :: "r"(dst), "l"(src));
}

__device__ __forceinline__ void load_chunk(uint32_t sbase, const float* __restrict__ W,
                                           int i_first, int buf, int tid) {
    const float* src0 = W + (size_t)i_first * (NJ * DI * DO);
    uint32_t d0 = sbase + (uint32_t)buf * (WBUF * 4);
    #pragma unroll 1
    for (int cidx = tid; cidx < G_ * NJ * 32; cidx += THREADS) {
        int q  = cidx & 31;
        int r  = cidx >> 5;           // 0..59
        int jj = r % NJ;
        int gg = r / NJ;
        const float* src = src0 + gg * (NJ * DI * DO) + jj * (DI * DO) + q * 4;
        uint32_t dst = d0 + (uint32_t)(gg * WTILE + jj * WROW + q * 4) * 4;
        cpa16(dst, src);
    }
    asm volatile("cp.async.commit_group;");
}

template <bool FIRST>
__global__ void __launch_bounds__(THREADS, 1)
sweep_kernel(const float* __restrict__ u, const float* __restrict__ W) {
    extern __shared__ float smem[];
    float* wst = smem;                       // W ring, 3 buffers
    float* vsm = smem + NBUF * WBUF;         // Vsum stage (padded rows)
    float* red = smem;                       // post-loop reduction staging (reuses W ring)

    const int tid  = threadIdx.x;
    const int warp = tid >> 5;
    const int lane = tid & 31;
    const int seg  = lane / 10;              // 0..2 active, 3 idle
    const bool active = (seg < 3);
    const int j    = lane - seg * 10;
    const int unit = warp * 3 + (active ? seg : 0);
    const int bp   = unit & 7;
    const int g    = unit >> 3;              // 0..5

    const int i0    = blockIdx.x * ICHUNK;
    const int bbase = blockIdx.y * BT;

    if (!FIRST) {
        for (int idx = tid; idx < BT * NJ * DO; idx += THREADS) {
            vsm[(idx >> 4) * VROW + (idx & 15)] = g_vsum[bbase * NJ * DO + idx];
        }
    }

    uint32_t smem_base = (uint32_t)__cvta_generic_to_shared(wst);

    load_chunk(smem_base, W, i0, 0, tid);
    load_chunk(smem_base, W, i0 + G_, 1, tid);

    ull sacc0[8], sacc1[8];
    #pragma unroll
    for (int k = 0; k < 8; k++) { sacc0[k] = 0ULL; sacc1[k] = 0ULL; }

    const int b0 = bbase + bp * 2;
    const float* u0p = u + (size_t)b0 * NI * DI;
    const float* u1p = u0p + (size_t)NI * DI;
    const float* vs0 = vsm + (bp * 2 * NJ + j) * VROW;
    const float* vs1 = vs0 + NJ * VROW;

    for (int c = 0; c < NCHUNK; c++) {
        const int buf = c % NBUF;
        const int i = i0 + c * G_ + g;

        // u loads early (independent of smem pipeline)
        float ur0[8], ur1[8];
        if (active) {
            float4 ua = *(const float4*)(u0p + (size_t)i * DI);
            float4 ub = *(const float4*)(u0p + (size_t)i * DI + 4);
            float4 uc = *(const float4*)(u1p + (size_t)i * DI);
            float4 ud = *(const float4*)(u1p + (size_t)i * DI + 4);
            ur0[0]=ua.x; ur0[1]=ua.y; ur0[2]=ua.z; ur0[3]=ua.w;
            ur0[4]=ub.x; ur0[5]=ub.y; ur0[6]=ub.z; ur0[7]=ub.w;
            ur1[0]=uc.x; ur1[1]=uc.y; ur1[2]=uc.z; ur1[3]=uc.w;
            ur1[4]=ud.x; ur1[5]=ud.y; ur1[6]=ud.z; ur1[7]=ud.w;
        }

        if (c + 1 < NCHUNK) asm volatile("cp.async.wait_group 1;");
        else                asm volatile("cp.async.wait_group 0;");
        __syncthreads();
        // refill ring slot (c+2)%3 == (c-1)%3: safe, all warps finished chunk c-1
        if (c + 2 < NCHUNK) load_chunk(smem_base, W, i0 + (c + 2) * G_, (c + 2) % NBUF, tid);

        if (active) {
            const float* wt = wst + buf * WBUF + g * WTILE + j * WROW;

            if (FIRST) {
                #pragma unroll
                for (int e = 0; e < 8; e++) {
                    ulonglong2 p0 = *(const ulonglong2*)(wt + e * 16);
                    ulonglong2 p1 = *(const ulonglong2*)(wt + e * 16 + 4);
                    ulonglong2 p2 = *(const ulonglong2*)(wt + e * 16 + 8);
                    ulonglong2 p3 = *(const ulonglong2*)(wt + e * 16 + 12);
                    ull ue0 = bcast2(ur0[e]);
                    ull ue1 = bcast2(ur1[e]);
                    sacc0[0] = fma2(ue0, p0.x, sacc0[0]); sacc1[0] = fma2(ue1, p0.x, sacc1[0]);
                    sacc0[1] = fma2(ue0, p0.y, sacc0[1]); sacc1[1] = fma2(ue1, p0.y, sacc1[1]);
                    sacc0[2] = fma2(ue0, p1.x, sacc0[2]); sacc1[2] = fma2(ue1, p1.x, sacc1[2]);
                    sacc0[3] = fma2(ue0, p1.y, sacc0[3]); sacc1[3] = fma2(ue1, p1.y, sacc1[3]);
                    sacc0[4] = fma2(ue0, p2.x, sacc0[4]); sacc1[4] = fma2(ue1, p2.x, sacc1[4]);
                    sacc0[5] = fma2(ue0, p2.y, sacc0[5]); sacc1[5] = fma2(ue1, p2.y, sacc1[5]);
                    sacc0[6] = fma2(ue0, p3.x, sacc0[6]); sacc1[6] = fma2(ue1, p3.x, sacc1[6]);
                    sacc0[7] = fma2(ue0, p3.y, sacc0[7]); sacc1[7] = fma2(ue1, p3.y, sacc1[7]);
                }
            } else {
                ull a0[8], a1[8];
                #pragma unroll
                for (int k = 0; k < 8; k++) { a0[k] = 0ULL; a1[k] = 0ULL; }
                #pragma unroll
                for (int e = 0; e < 8; e++) {
                    ulonglong2 p0 = *(const ulonglong2*)(wt + e * 16);
                    ulonglong2 p1 = *(const ulonglong2*)(wt + e * 16 + 4);
                    ulonglong2 p2 = *(const ulonglong2*)(wt + e * 16 + 8);
                    ulonglong2 p3 = *(const ulonglong2*)(wt + e * 16 + 12);
                    ull ue0 = bcast2(ur0[e]);
                    ull ue1 = bcast2(ur1[e]);
                    a0[0] = fma2(ue0, p0.x, a0[0]); a1[0] = fma2(ue1, p0.x, a1[0]);
                    a0[1] = fma2(ue0, p0.y, a0[1]); a1[1] = fma2(ue1, p0.y, a1[1]);
                    a0[2] = fma2(ue0, p1.x, a0[2]); a1[2] = fma2(ue1, p1.x, a1[2]);
                    a0[3] = fma2(ue0, p1.y, a0[3]); a1[3] = fma2(ue1, p1.y, a1[3]);
                    a0[4] = fma2(ue0, p2.x, a0[4]); a1[4] = fma2(ue1, p2.x, a1[4]);
                    a0[5] = fma2(ue0, p2.y, a0[5]); a1[5] = fma2(ue1, p2.y, a1[5]);
                    a0[6] = fma2(ue0, p3.x, a0[6]); a1[6] = fma2(ue1, p3.x, a1[6]);
                    a0[7] = fma2(ue0, p3.y, a0[7]); a1[7] = fma2(ue1, p3.y, a1[7]);
                }

                ull d0 = 0ULL, d1 = 0ULL;
                #pragma unroll
                for (int k = 0; k < 8; k++) {
                    ull v0 = ((const ull*)vs0)[k];
                    ull v1 = ((const ull*)vs1)[k];
                    d0 = fma2(a0[k], v0, d0);
                    d1 = fma2(a1[k], v1, d1);
                }
                float l0 = sum2(d0), l1 = sum2(d1);
                float e0 = __expf(l0), e1 = __expf(l1);
                float t0 = 0.f, t1 = 0.f;
                const int base = seg * 10;
                #pragma unroll
                for (int jj = 0; jj < 10; jj++) {
                    t0 += __shfl_sync(0x3FFFFFFFu, e0, base + jj);
                    t1 += __shfl_sync(0x3FFFFFFFu, e1, base + jj);
                }
                ull c0 = bcast2(e0 / t0);
                ull c1 = bcast2(e1 / t1);
                #pragma unroll
                for (int k = 0; k < 8; k++) {
                    sacc0[k] = fma2(c0, a0[k], sacc0[k]);
                    sacc1[k] = fma2(c1, a1[k], sacc1[k]);
                }
            }
        }
    }

    // ---- in-block reduction over g (6 partials) ----
    __syncthreads();   // everyone done reading W ring; reuse it as staging
    if (active) {
        int r0 = ((bp * 6 + g) * 2 + 0) * 10 + j;
        int r1 = r0 + 10;
        #pragma unroll
        for (int k = 0; k < 8; k++) {
            st2(red + r0 * 16 + 2 * k, sacc0[k]);
            st2(red + r1 * 16 + 2 * k, sacc1[k]);
        }
    }
    __syncthreads();

    #pragma unroll 1
    for (int idx = tid; idx < BT * NJ * DO; idx += THREADS) {
        int d  = idx & 15;
        int r  = idx >> 4;
        int jj = r % 10;
        int r2 = r / 10;
        int bb = r2 & 1;
        int bpp = r2 >> 1;
        float s = 0.f;
        #pragma unroll
        for (int gg = 0; gg < 6; gg++)
            s += red[(((bpp * 6 + gg) * 2 + bb) * 10 + jj) * 16 + d];
        if (FIRST) s *= 0.1f;
        int b = bbase + bpp * 2 + bb;
        g_partial[((size_t)(b * NPART + blockIdx.x) * NJ + jj) * DO + d] = s;
    }
}

template <bool FIRST, bool LAST>
__global__ void reduce_kernel(float* __restrict__ out) {
    int t = blockIdx.x * blockDim.x + threadIdx.x;
    if (t >= B_ * NJ * 4) return;
    int q = t & 3;
    int j = (t >> 2) % NJ;
    int b = t / (NJ * 4);

    const float4* src = (const float4*)g_partial + ((size_t)(b * NPART) * NJ + j) * 4 + q;
    float4 acc = make_float4(0.f, 0.f, 0.f, 0.f);
    #pragma unroll
    for (int p = 0; p < NPART; p++) {
        float4 x = src[(size_t)p * NJ * 4];
        acc.x += x.x; acc.y += x.y; acc.z += x.z; acc.w += x.w;
    }

    float sq = acc.x * acc.x + acc.y * acc.y + acc.z * acc.z + acc.w * acc.w;
    sq += __shfl_xor_sync(0xFFFFFFFFu, sq, 1);
    sq += __shfl_xor_sync(0xFFFFFFFFu, sq, 2);
    float norm = sqrtf(sq);
    float factor = sq / (norm * (1.f + sq));

    float4 v = make_float4(factor * acc.x, factor * acc.y, factor * acc.z, factor * acc.w);
    if (LAST) {
        ((float4*)out)[(size_t)(b * NJ + j) * 4 + q] = v;
    } else {
        float4* vp = (float4*)g_vsum + (b * NJ + j) * 4 + q;
        if (FIRST) {
            *vp = v;
        } else {
            float4 o = *vp;
            *vp = make_float4(o.x + v.x, o.y + v.y, o.z + v.z, o.w + v.w);
        }
    }
}

extern "C" void kernel_launch(void* const* d_in, const int* in_sizes, int n_in,
                              void* d_out, int out_size) {
    const float* u = (const float*)d_in[0];
    const float* W = (const float*)d_in[1];
    float* out = (float*)d_out;

    const int smem = SMEM_WORDS * 4;  // 106560 B
    cudaFuncSetAttribute(sweep_kernel<true>,  cudaFuncAttributeMaxDynamicSharedMemorySize, smem);
    cudaFuncSetAttribute(sweep_kernel<false>, cudaFuncAttributeMaxDynamicSharedMemorySize, smem);

    dim3 grid(ISPLITS, B_ / BT);
    const int rblocks = (B_ * NJ * 4 + 255) / 256;  // 80

    sweep_kernel<true><<<grid, THREADS, smem>>>(u, W);
    reduce_kernel<true, false><<<rblocks, 256>>>(out);
    sweep_kernel<false><<<grid, THREADS, smem>>>(u, W);
    reduce_kernel<false, false><<<rblocks, 256>>>(out);
    sweep_kernel<false><<<grid, THREADS, smem>>>(u, W);
    reduce_kernel<false, true><<<rblocks, 256>>>(out);
}

// round 3
// speedup vs baseline: 1.3412x; 1.0582x over previous
#include <cuda_runtime.h>
#include <cstdint>

// DigitCaps dynamic routing, fused.
// b_t[i,j] = u_hat[b,i,j,:] . Vsum_t[b,j,:], Vsum_t = sum_{tau<t} v_tau
// W staged into padded SMEM via cp.async.bulk (TMA) + mbarrier, 3-slot ring.

#define B_      512
#define NI      1152
#define NJ      10
#define DI      8
#define DO      16

#define THREADS 512
#define BT      16       // batches per block (8 pairs)
#define G_      6        // i's per chunk
#define ISPLITS 8
#define ICHUNK  144      // NI / ISPLITS
#define NCHUNK  24       // ICHUNK / G_
#define NPART   ISPLITS  // 8 partials per (b,j)

#define WROW    132              // 128 + 4 pad words (528 B, 16B-aligned)
#define WTILE   (NJ * WROW)      // 1320 words per i
#define WBUF    (G_ * WTILE)     // 7920 words per ring slot
#define NBUF    3
#define VROW    18
#define CHUNK_BYTES (G_ * NJ * 512)   // 30720
// ring 23760 + vsum 2880 + mbar 8 words
#define SMEM_WORDS (NBUF * WBUF + BT * NJ * VROW + 8)

__device__ float g_partial[(size_t)B_ * NPART * NJ * DO];
__device__ float g_vsum[B_ * NJ * DO];

using ull = unsigned long long;

__device__ __forceinline__ ull fma2(ull a, ull b, ull c) {
    ull d; asm("fma.rn.f32x2 %0, %1, %2, %3;" : "=l"(d) : "l"(a), "l"(b), "l"(c)); return d;
}
__device__ __forceinline__ ull bcast2(float x) {
    ull d; asm("mov.b64 %0, {%1, %1};" : "=l"(d) : "f"(x)); return d;
}
__device__ __forceinline__ float sum2(ull a) {
    float l, h; asm("mov.b64 {%0, %1}, %2;" : "=f"(l), "=f"(h) : "l"(a)); return l + h;
}
__device__ __forceinline__ void st2(float* p, ull v) { *(ull*)p = v; }

__device__ __forceinline__ void mbar_init(uint32_t addr, uint32_t count) {
    asm volatile("mbarrier.init.shared.b64 [%0], %1;" :: "r"(addr), "r"(count) : "memory");
}
__device__ __forceinline__ void mbar_wait(uint32_t addr, uint32_t parity) {
    asm volatile(
        "{\n\t.reg .pred P;\n\t"
        "WL_%=:\n\t"
        "mbarrier.try_wait.parity.acquire.cta.shared::cta.b64 P, [%0], %1, 0x989680;\n\t"
        "@P bra.uni WD_%=;\n\t"
        "bra.uni WL_%=;\n\t"
        "WD_%=:\n\t}"
        :: "r"(addr), "r"(parity) : "memory");
}

// 60 bulk copies of 512B each: W row (i,j) -> padded smem row.
__device__ __forceinline__ void issue_chunk(const float* __restrict__ W, int i_first,
                                            int slot, uint32_t sbase, uint32_t mbase,
                                            int tid) {
    uint32_t mbar = mbase + slot * 8;
    if (tid == 0) {
        asm volatile("mbarrier.arrive.expect_tx.shared.b64 _, [%0], %1;"
                     :: "r"(mbar), "r"((uint32_t)CHUNK_BYTES) : "memory");
    }
    if (tid < G_ * NJ) {
        int gg = tid / NJ;
        int jj = tid - gg * NJ;
        const float* src = W + ((size_t)(i_first + gg) * NJ + jj) * (DI * DO);
        uint32_t dst = sbase + (uint32_t)(slot * WBUF + gg * WTILE + jj * WROW) * 4;
        asm volatile(
            "cp.async.bulk.shared::cluster.global.mbarrier::complete_tx::bytes "
            "[%0], [%1], %2, [%3];"
            :: "r"(dst), "l"(src), "r"((uint32_t)512), "r"(mbar) : "memory");
    }
}

template <bool FIRST>
__global__ void __launch_bounds__(THREADS, 1)
sweep_kernel(const float* __restrict__ u, const float* __restrict__ W) {
    extern __shared__ float smem[];
    float* wst = smem;                       // W ring, 3 slots
    float* vsm = smem + NBUF * WBUF;         // Vsum stage (padded rows)
    float* red = smem;                       // post-loop staging (reuses ring)

    const int tid  = threadIdx.x;
    const int lane = tid & 31;
    const int warp = tid >> 5;
    const int seg  = lane / 10;              // 0..2 active, 3 idle
    const bool active = (seg < 3);
    const int j    = lane - seg * 10;
    const int unit = warp * 3 + (active ? seg : 0);
    const int bp   = unit & 7;
    const int g    = unit >> 3;              // 0..5

    const int i0    = blockIdx.x * ICHUNK;
    const int bbase = blockIdx.y * BT;

    uint32_t smem_base = (uint32_t)__cvta_generic_to_shared(wst);
    uint32_t mbar_base = (uint32_t)__cvta_generic_to_shared(smem + NBUF * WBUF + BT * NJ * VROW);

    if (tid == 0) {
        mbar_init(mbar_base + 0, 1);
        mbar_init(mbar_base + 8, 1);
        mbar_init(mbar_base + 16, 1);
    }
    if (!FIRST) {
        for (int idx = tid; idx < BT * NJ * DO; idx += THREADS) {
            vsm[(idx >> 4) * VROW + (idx & 15)] = g_vsum[bbase * NJ * DO + idx];
        }
    }
    __syncthreads();

    issue_chunk(W, i0, 0, smem_base, mbar_base, tid);
    issue_chunk(W, i0 + G_, 1, smem_base, mbar_base, tid);

    ull sacc0[8], sacc1[8];
    #pragma unroll
    for (int k = 0; k < 8; k++) { sacc0[k] = 0ULL; sacc1[k] = 0ULL; }

    const int b0 = bbase + bp * 2;
    const float* u0p = u + (size_t)b0 * NI * DI;
    const float* u1p = u0p + (size_t)NI * DI;
    const float* vs0 = vsm + (bp * 2 * NJ + j) * VROW;
    const float* vs1 = vs0 + NJ * VROW;

    for (int c = 0; c < NCHUNK; c++) {
        const int buf = c % NBUF;
        const int i = i0 + c * G_ + g;

        // u loads early (L1/L2, independent of smem pipeline)
        float ur0[8], ur1[8];
        if (active) {
            float4 ua = *(const float4*)(u0p + (size_t)i * DI);
            float4 ub = *(const float4*)(u0p + (size_t)i * DI + 4);
            float4 uc = *(const float4*)(u1p + (size_t)i * DI);
            float4 ud = *(const float4*)(u1p + (size_t)i * DI + 4);
            ur0[0]=ua.x; ur0[1]=ua.y; ur0[2]=ua.z; ur0[3]=ua.w;
            ur0[4]=ub.x; ur0[5]=ub.y; ur0[6]=ub.z; ur0[7]=ub.w;
            ur1[0]=uc.x; ur1[1]=uc.y; ur1[2]=uc.z; ur1[3]=uc.w;
            ur1[4]=ud.x; ur1[5]=ud.y; ur1[6]=ud.z; ur1[7]=ud.w;
        }

        __syncthreads();   // all threads done computing chunk c-1 -> slot (c+2)%3 reusable
        if (c + 2 < NCHUNK)
            issue_chunk(W, i0 + (c + 2) * G_, (c + 2) % NBUF, smem_base, mbar_base, tid);

        mbar_wait(mbar_base + buf * 8, (c / NBUF) & 1);

        if (active) {
            const float* wt = wst + buf * WBUF + g * WTILE + j * WROW;

            if (FIRST) {
                #pragma unroll
                for (int e = 0; e < 8; e++) {
                    ulonglong2 p0 = *(const ulonglong2*)(wt + e * 16);
                    ulonglong2 p1 = *(const ulonglong2*)(wt + e * 16 + 4);
                    ulonglong2 p2 = *(const ulonglong2*)(wt + e * 16 + 8);
                    ulonglong2 p3 = *(const ulonglong2*)(wt + e * 16 + 12);
                    ull ue0 = bcast2(ur0[e]);
                    ull ue1 = bcast2(ur1[e]);
                    sacc0[0] = fma2(ue0, p0.x, sacc0[0]); sacc1[0] = fma2(ue1, p0.x, sacc1[0]);
                    sacc0[1] = fma2(ue0, p0.y, sacc0[1]); sacc1[1] = fma2(ue1, p0.y, sacc1[1]);
                    sacc0[2] = fma2(ue0, p1.x, sacc0[2]); sacc1[2] = fma2(ue1, p1.x, sacc1[2]);
                    sacc0[3] = fma2(ue0, p1.y, sacc0[3]); sacc1[3] = fma2(ue1, p1.y, sacc1[3]);
                    sacc0[4] = fma2(ue0, p2.x, sacc0[4]); sacc1[4] = fma2(ue1, p2.x, sacc1[4]);
                    sacc0[5] = fma2(ue0, p2.y, sacc0[5]); sacc1[5] = fma2(ue1, p2.y, sacc1[5]);
                    sacc0[6] = fma2(ue0, p3.x, sacc0[6]); sacc1[6] = fma2(ue1, p3.x, sacc1[6]);
                    sacc0[7] = fma2(ue0, p3.y, sacc0[7]); sacc1[7] = fma2(ue1, p3.y, sacc1[7]);
                }
            } else {
                ull a0[8], a1[8];
                #pragma unroll
                for (int k = 0; k < 8; k++) { a0[k] = 0ULL; a1[k] = 0ULL; }
                #pragma unroll
                for (int e = 0; e < 8; e++) {
                    ulonglong2 p0 = *(const ulonglong2*)(wt + e * 16);
                    ulonglong2 p1 = *(const ulonglong2*)(wt + e * 16 + 4);
                    ulonglong2 p2 = *(const ulonglong2*)(wt + e * 16 + 8);
                    ulonglong2 p3 = *(const ulonglong2*)(wt + e * 16 + 12);
                    ull ue0 = bcast2(ur0[e]);
                    ull ue1 = bcast2(ur1[e]);
                    a0[0] = fma2(ue0, p0.x, a0[0]); a1[0] = fma2(ue1, p0.x, a1[0]);
                    a0[1] = fma2(ue0, p0.y, a0[1]); a1[1] = fma2(ue1, p0.y, a1[1]);
                    a0[2] = fma2(ue0, p1.x, a0[2]); a1[2] = fma2(ue1, p1.x, a1[2]);
                    a0[3] = fma2(ue0, p1.y, a0[3]); a1[3] = fma2(ue1, p1.y, a1[3]);
                    a0[4] = fma2(ue0, p2.x, a0[4]); a1[4] = fma2(ue1, p2.x, a1[4]);
                    a0[5] = fma2(ue0, p2.y, a0[5]); a1[5] = fma2(ue1, p2.y, a1[5]);
                    a0[6] = fma2(ue0, p3.x, a0[6]); a1[6] = fma2(ue1, p3.x, a1[6]);
                    a0[7] = fma2(ue0, p3.y, a0[7]); a1[7] = fma2(ue1, p3.y, a1[7]);
                }

                ull d0 = 0ULL, d1 = 0ULL;
                #pragma unroll
                for (int k = 0; k < 8; k++) {
                    ull v0 = ((const ull*)vs0)[k];
                    ull v1 = ((const ull*)vs1)[k];
                    d0 = fma2(a0[k], v0, d0);
                    d1 = fma2(a1[k], v1, d1);
                }
                float l0 = sum2(d0), l1 = sum2(d1);
                float e0 = __expf(l0), e1 = __expf(l1);
                float t0 = 0.f, t1 = 0.f;
                const int base = seg * 10;
                #pragma unroll
                for (int jj = 0; jj < 10; jj++) {
                    t0 += __shfl_sync(0x3FFFFFFFu, e0, base + jj);
                    t1 += __shfl_sync(0x3FFFFFFFu, e1, base + jj);
                }
                ull c0 = bcast2(e0 / t0);
                ull c1 = bcast2(e1 / t1);
                #pragma unroll
                for (int k = 0; k < 8; k++) {
                    sacc0[k] = fma2(c0, a0[k], sacc0[k]);
                    sacc1[k] = fma2(c1, a1[k], sacc1[k]);
                }
            }
        }
    }

    // ---- in-block reduction over g (6 partials per (b,j)) ----
    __syncthreads();   // ring fully consumed; reuse as staging
    if (active) {
        int r0 = ((bp * 6 + g) * 2 + 0) * 10 + j;
        int r1 = r0 + 10;
        #pragma unroll
        for (int k = 0; k < 8; k++) {
            st2(red + r0 * 16 + 2 * k, sacc0[k]);
            st2(red + r1 * 16 + 2 * k, sacc1[k]);
        }
    }
    __syncthreads();

    #pragma unroll 1
    for (int idx = tid; idx < BT * NJ * DO; idx += THREADS) {
        int d  = idx & 15;
        int r  = idx >> 4;
        int jj = r % 10;
        int r2 = r / 10;
        int bb = r2 & 1;
        int bpp = r2 >> 1;
        float s = 0.f;
        #pragma unroll
        for (int gg = 0; gg < 6; gg++)
            s += red[(((bpp * 6 + gg) * 2 + bb) * 10 + jj) * 16 + d];
        if (FIRST) s *= 0.1f;
        int b = bbase + bpp * 2 + bb;
        g_partial[((size_t)(b * NPART + blockIdx.x) * NJ + jj) * DO + d] = s;
    }
}

template <bool FIRST, bool LAST>
__global__ void reduce_kernel(float* __restrict__ out) {
    int t = blockIdx.x * blockDim.x + threadIdx.x;
    if (t >= B_ * NJ * 4) return;
    int q = t & 3;
    int j = (t >> 2) % NJ;
    int b = t / (NJ * 4);

    const float4* src = (const float4*)g_partial + ((size_t)(b * NPART) * NJ + j) * 4 + q;
    float4 acc = make_float4(0.f, 0.f, 0.f, 0.f);
    #pragma unroll
    for (int p = 0; p < NPART; p++) {
        float4 x = src[(size_t)p * NJ * 4];
        acc.x += x.x; acc.y += x.y; acc.z += x.z; acc.w += x.w;
    }

    float sq = acc.x * acc.x + acc.y * acc.y + acc.z * acc.z + acc.w * acc.w;
    sq += __shfl_xor_sync(0xFFFFFFFFu, sq, 1);
    sq += __shfl_xor_sync(0xFFFFFFFFu, sq, 2);
    float norm = sqrtf(sq);
    float factor = sq / (norm * (1.f + sq));

    float4 v = make_float4(factor * acc.x, factor * acc.y, factor * acc.z, factor * acc.w);
    if (LAST) {
        ((float4*)out)[(size_t)(b * NJ + j) * 4 + q] = v;
    } else {
        float4* vp = (float4*)g_vsum + (b * NJ + j) * 4 + q;
        if (FIRST) {
            *vp = v;
        } else {
            float4 o = *vp;
            *vp = make_float4(o.x + v.x, o.y + v.y, o.z + v.z, o.w + v.w);
        }
    }
}

extern "C" void kernel_launch(void* const* d_in, const int* in_sizes, int n_in,
                              void* d_out, int out_size) {
    const float* u = (const float*)d_in[0];
    const float* W = (const float*)d_in[1];
    float* out = (float*)d_out;

    const int smem = SMEM_WORDS * 4;
    cudaFuncSetAttribute(sweep_kernel<true>,  cudaFuncAttributeMaxDynamicSharedMemorySize, smem);
    cudaFuncSetAttribute(sweep_kernel<false>, cudaFuncAttributeMaxDynamicSharedMemorySize, smem);

    dim3 grid(ISPLITS, B_ / BT);
    const int rblocks = (B_ * NJ * 4 + 255) / 256;  // 80

    sweep_kernel<true><<<grid, THREADS, smem>>>(u, W);
    reduce_kernel<true, false><<<rblocks, 256>>>(out);
    sweep_kernel<false><<<grid, THREADS, smem>>>(u, W);
    reduce_kernel<false, false><<<rblocks, 256>>>(out);
    sweep_kernel<false><<<grid, THREADS, smem>>>(u, W);
    reduce_kernel<false, true><<<rblocks, 256>>>(out);
}

// round 4
// speedup vs baseline: 1.3709x; 1.0221x over previous
#include <cuda_runtime.h>
#include <cstdint>

// DigitCaps dynamic routing, fused.
// b_t[i,j] = u_hat[b,i,j,:] . Vsum_t[b,j,:], Vsum_t = sum_{tau<t} v_tau
// W pre-padded in gmem once -> ONE cp.async.bulk per chunk into smem ring.

#define B_      512
#define NI      1152
#define NJ      10
#define DI      8
#define DO      16

#define THREADS 512
#define BT      16       // batches per block (8 pairs)
#define G_      6        // i's per chunk
#define ISPLITS 8
#define ICHUNK  144      // NI / ISPLITS
#define NCHUNK  24       // ICHUNK / G_
#define NCHUNK_TOTAL (ISPLITS * NCHUNK)   // 192
#define NPART   ISPLITS  // 8 partials per (b,j)

#define WROW    132              // 128 + 4 pad words
#define WTILE   (NJ * WROW)      // 1320 words per i
#define WBUF    (G_ * WTILE)     // 7920 words per ring slot
#define NBUF    3
#define VROW    18
#define CHUNK_BYTES (WBUF * 4)   // 31680
#define SMEM_WORDS (NBUF * WBUF + BT * NJ * VROW + 8)

__device__ float g_wpad[(size_t)NCHUNK_TOTAL * WBUF];      // ~6.1 MB padded W image
__device__ float g_partial[(size_t)B_ * NPART * NJ * DO];
__device__ float g_vsum[B_ * NJ * DO];

using ull = unsigned long long;

__device__ __forceinline__ ull fma2(ull a, ull b, ull c) {
    ull d; asm("fma.rn.f32x2 %0, %1, %2, %3;" : "=l"(d) : "l"(a), "l"(b), "l"(c)); return d;
}
__device__ __forceinline__ ull bcast2(float x) {
    ull d; asm("mov.b64 %0, {%1, %1};" : "=l"(d) : "f"(x)); return d;
}
__device__ __forceinline__ float sum2(ull a) {
    float l, h; asm("mov.b64 {%0, %1}, %2;" : "=f"(l), "=f"(h) : "l"(a)); return l + h;
}
__device__ __forceinline__ void st2(float* p, ull v) { *(ull*)p = v; }

__device__ __forceinline__ void mbar_init(uint32_t addr, uint32_t count) {
    asm volatile("mbarrier.init.shared.b64 [%0], %1;" :: "r"(addr), "r"(count) : "memory");
}
__device__ __forceinline__ void mbar_wait(uint32_t addr, uint32_t parity) {
    asm volatile(
        "{\n\t.reg .pred P;\n\t"
        "WL_%=:\n\t"
        "mbarrier.try_wait.parity.acquire.cta.shared::cta.b64 P, [%0], %1, 0x989680;\n\t"
        "@P bra.uni WD_%=;\n\t"
        "bra.uni WL_%=;\n\t"
        "WD_%=:\n\t}"
        :: "r"(addr), "r"(parity) : "memory");
}

// ONE bulk copy per chunk: padded tile image -> ring slot.
__device__ __forceinline__ void issue_chunk(int chunk, int slot,
                                            uint32_t sbase, uint32_t mbase, int tid) {
    if (tid == 0) {
        uint32_t mbar = mbase + slot * 8;
        asm volatile("mbarrier.arrive.expect_tx.shared.b64 _, [%0], %1;"
                     :: "r"(mbar), "r"((uint32_t)CHUNK_BYTES) : "memory");
        const float* src = g_wpad + (size_t)chunk * WBUF;
        uint32_t dst = sbase + (uint32_t)(slot * WBUF) * 4;
        asm volatile(
            "cp.async.bulk.shared::cluster.global.mbarrier::complete_tx::bytes "
            "[%0], [%1], %2, [%3];"
            :: "r"(dst), "l"(src), "r"((uint32_t)CHUNK_BYTES), "r"(mbar) : "memory");
    }
}

// W[i][j][e][d] -> g_wpad[chunk][(g*10+j)*132 + e*16 + d], pad words zeroed.
__global__ void prepack_kernel(const float* __restrict__ W) {
    int idx = blockIdx.x * blockDim.x + threadIdx.x;     // quad index
    const int total = NCHUNK_TOTAL * G_ * NJ * 33;       // 380160
    if (idx >= total) return;
    int q = idx % 33;
    int r = idx / 33;          // global row = chunk*60 + g*10 + j
    int row_in_chunk = r % (G_ * NJ);
    int chunk = r / (G_ * NJ);
    int g = row_in_chunk / NJ;
    int j = row_in_chunk - g * NJ;
    float4 v = make_float4(0.f, 0.f, 0.f, 0.f);
    if (q < 32) {
        int i = chunk * G_ + g;
        v = ((const float4*)W)[(size_t)(i * NJ + j) * 32 + q];
    }
    ((float4*)g_wpad)[(size_t)r * 33 + q] = v;
}

template <bool FIRST>
__global__ void __launch_bounds__(THREADS, 1)
sweep_kernel(const float* __restrict__ u) {
    extern __shared__ float smem[];
    float* wst = smem;                       // W ring, 3 slots
    float* vsm = smem + NBUF * WBUF;         // Vsum stage (padded rows)
    float* red = smem;                       // post-loop staging (reuses ring)

    const int tid  = threadIdx.x;
    const int lane = tid & 31;
    const int warp = tid >> 5;
    const int seg  = lane / 10;              // 0..2 active, 3 idle
    const bool active = (seg < 3);
    const int j    = lane - seg * 10;
    const int unit = warp * 3 + (active ? seg : 0);
    const int bp   = unit & 7;
    const int g    = unit >> 3;              // 0..5

    const int c0g   = blockIdx.x * NCHUNK;   // first global chunk of this i-split
    const int i0    = blockIdx.x * ICHUNK;
    const int bbase = blockIdx.y * BT;

    uint32_t smem_base = (uint32_t)__cvta_generic_to_shared(wst);
    uint32_t mbar_base = (uint32_t)__cvta_generic_to_shared(smem + NBUF * WBUF + BT * NJ * VROW);

    if (tid == 0) {
        mbar_init(mbar_base + 0, 1);
        mbar_init(mbar_base + 8, 1);
        mbar_init(mbar_base + 16, 1);
    }
    if (!FIRST) {
        for (int idx = tid; idx < BT * NJ * DO; idx += THREADS) {
            vsm[(idx >> 4) * VROW + (idx & 15)] = g_vsum[bbase * NJ * DO + idx];
        }
    }
    __syncthreads();

    issue_chunk(c0g, 0, smem_base, mbar_base, tid);
    issue_chunk(c0g + 1, 1, smem_base, mbar_base, tid);

    ull sacc0[8], sacc1[8];
    #pragma unroll
    for (int k = 0; k < 8; k++) { sacc0[k] = 0ULL; sacc1[k] = 0ULL; }

    const int b0 = bbase + bp * 2;
    const float* u0p = u + (size_t)b0 * NI * DI;
    const float* u1p = u0p + (size_t)NI * DI;
    const float* vs0 = vsm + (bp * 2 * NJ + j) * VROW;
    const float* vs1 = vs0 + NJ * VROW;

    for (int c = 0; c < NCHUNK; c++) {
        const int buf = c % NBUF;
        const int i = i0 + c * G_ + g;

        float ur0[8], ur1[8];
        if (active) {
            float4 ua = *(const float4*)(u0p + (size_t)i * DI);
            float4 ub = *(const float4*)(u0p + (size_t)i * DI + 4);
            float4 uc = *(const float4*)(u1p + (size_t)i * DI);
            float4 ud = *(const float4*)(u1p + (size_t)i * DI + 4);
            ur0[0]=ua.x; ur0[1]=ua.y; ur0[2]=ua.z; ur0[3]=ua.w;
            ur0[4]=ub.x; ur0[5]=ub.y; ur0[6]=ub.z; ur0[7]=ub.w;
            ur1[0]=uc.x; ur1[1]=uc.y; ur1[2]=uc.z; ur1[3]=uc.w;
            ur1[4]=ud.x; ur1[5]=ud.y; ur1[6]=ud.z; ur1[7]=ud.w;
        }

        __syncthreads();   // all warps done with chunk c-1 -> its slot is reusable
        if (c + 2 < NCHUNK)
            issue_chunk(c0g + c + 2, (c + 2) % NBUF, smem_base, mbar_base, tid);

        mbar_wait(mbar_base + buf * 8, (c / NBUF) & 1);

        if (active) {
            const float* wt = wst + buf * WBUF + g * WTILE + j * WROW;

            if (FIRST) {
                #pragma unroll
                for (int e = 0; e < 8; e++) {
                    ulonglong2 p0 = *(const ulonglong2*)(wt + e * 16);
                    ulonglong2 p1 = *(const ulonglong2*)(wt + e * 16 + 4);
                    ulonglong2 p2 = *(const ulonglong2*)(wt + e * 16 + 8);
                    ulonglong2 p3 = *(const ulonglong2*)(wt + e * 16 + 12);
                    ull ue0 = bcast2(ur0[e]);
                    ull ue1 = bcast2(ur1[e]);
                    sacc0[0] = fma2(ue0, p0.x, sacc0[0]); sacc1[0] = fma2(ue1, p0.x, sacc1[0]);
                    sacc0[1] = fma2(ue0, p0.y, sacc0[1]); sacc1[1] = fma2(ue1, p0.y, sacc1[1]);
                    sacc0[2] = fma2(ue0, p1.x, sacc0[2]); sacc1[2] = fma2(ue1, p1.x, sacc1[2]);
                    sacc0[3] = fma2(ue0, p1.y, sacc0[3]); sacc1[3] = fma2(ue1, p1.y, sacc1[3]);
                    sacc0[4] = fma2(ue0, p2.x, sacc0[4]); sacc1[4] = fma2(ue1, p2.x, sacc1[4]);
                    sacc0[5] = fma2(ue0, p2.y, sacc0[5]); sacc1[5] = fma2(ue1, p2.y, sacc1[5]);
                    sacc0[6] = fma2(ue0, p3.x, sacc0[6]); sacc1[6] = fma2(ue1, p3.x, sacc1[6]);
                    sacc0[7] = fma2(ue0, p3.y, sacc0[7]); sacc1[7] = fma2(ue1, p3.y, sacc1[7]);
                }
            } else {
                ull a0[8], a1[8];
                #pragma unroll
                for (int k = 0; k < 8; k++) { a0[k] = 0ULL; a1[k] = 0ULL; }
                #pragma unroll
                for (int e = 0; e < 8; e++) {
                    ulonglong2 p0 = *(const ulonglong2*)(wt + e * 16);
                    ulonglong2 p1 = *(const ulonglong2*)(wt + e * 16 + 4);
                    ulonglong2 p2 = *(const ulonglong2*)(wt + e * 16 + 8);
                    ulonglong2 p3 = *(const ulonglong2*)(wt + e * 16 + 12);
                    ull ue0 = bcast2(ur0[e]);
                    ull ue1 = bcast2(ur1[e]);
                    a0[0] = fma2(ue0, p0.x, a0[0]); a1[0] = fma2(ue1, p0.x, a1[0]);
                    a0[1] = fma2(ue0, p0.y, a0[1]); a1[1] = fma2(ue1, p0.y, a1[1]);
                    a0[2] = fma2(ue0, p1.x, a0[2]); a1[2] = fma2(ue1, p1.x, a1[2]);
                    a0[3] = fma2(ue0, p1.y, a0[3]); a1[3] = fma2(ue1, p1.y, a1[3]);
                    a0[4] = fma2(ue0, p2.x, a0[4]); a1[4] = fma2(ue1, p2.x, a1[4]);
                    a0[5] = fma2(ue0, p2.y, a0[5]); a1[5] = fma2(ue1, p2.y, a1[5]);
                    a0[6] = fma2(ue0, p3.x, a0[6]); a1[6] = fma2(ue1, p3.x, a1[6]);
                    a0[7] = fma2(ue0, p3.y, a0[7]); a1[7] = fma2(ue1, p3.y, a1[7]);
                }

                ull d0 = 0ULL, d1 = 0ULL;
                #pragma unroll
                for (int k = 0; k < 8; k++) {
                    ull v0 = ((const ull*)vs0)[k];
                    ull v1 = ((const ull*)vs1)[k];
                    d0 = fma2(a0[k], v0, d0);
                    d1 = fma2(a1[k], v1, d1);
                }
                float l0 = sum2(d0), l1 = sum2(d1);
                float e0 = __expf(l0), e1 = __expf(l1);
                float t0 = 0.f, t1 = 0.f;
                const int base = seg * 10;
                #pragma unroll
                for (int jj = 0; jj < 10; jj++) {
                    t0 += __shfl_sync(0x3FFFFFFFu, e0, base + jj);
                    t1 += __shfl_sync(0x3FFFFFFFu, e1, base + jj);
                }
                ull c0 = bcast2(e0 / t0);
                ull c1 = bcast2(e1 / t1);
                #pragma unroll
                for (int k = 0; k < 8; k++) {
                    sacc0[k] = fma2(c0, a0[k], sacc0[k]);
                    sacc1[k] = fma2(c1, a1[k], sacc1[k]);
                }
            }
        }
    }

    // ---- in-block reduction over g ----
    __syncthreads();
    if (active) {
        int r0 = ((bp * 6 + g) * 2 + 0) * 10 + j;
        int r1 = r0 + 10;
        #pragma unroll
        for (int k = 0; k < 8; k++) {
            st2(red + r0 * 16 + 2 * k, sacc0[k]);
            st2(red + r1 * 16 + 2 * k, sacc1[k]);
        }
    }
    __syncthreads();

    #pragma unroll 1
    for (int idx = tid; idx < BT * NJ * DO; idx += THREADS) {
        int d  = idx & 15;
        int r  = idx >> 4;
        int jj = r % 10;
        int r2 = r / 10;
        int bb = r2 & 1;
        int bpp = r2 >> 1;
        float s = 0.f;
        #pragma unroll
        for (int gg = 0; gg < 6; gg++)
            s += red[(((bpp * 6 + gg) * 2 + bb) * 10 + jj) * 16 + d];
        if (FIRST) s *= 0.1f;
        int b = bbase + bpp * 2 + bb;
        g_partial[((size_t)(b * NPART + blockIdx.x) * NJ + jj) * DO + d] = s;
    }
}

template <bool FIRST, bool LAST>
__global__ void reduce_kernel(float* __restrict__ out) {
    int t = blockIdx.x * blockDim.x + threadIdx.x;
    if (t >= B_ * NJ * 4) return;
    int q = t & 3;
    int j = (t >> 2) % NJ;
    int b = t / (NJ * 4);

    const float4* src = (const float4*)g_partial + ((size_t)(b * NPART) * NJ + j) * 4 + q;
    float4 acc = make_float4(0.f, 0.f, 0.f, 0.f);
    #pragma unroll
    for (int p = 0; p < NPART; p++) {
        float4 x = src[(size_t)p * NJ * 4];
        acc.x += x.x; acc.y += x.y; acc.z += x.z; acc.w += x.w;
    }

    float sq = acc.x * acc.x + acc.y * acc.y + acc.z * acc.z + acc.w * acc.w;
    sq += __shfl_xor_sync(0xFFFFFFFFu, sq, 1);
    sq += __shfl_xor_sync(0xFFFFFFFFu, sq, 2);
    float norm = sqrtf(sq);
    float factor = sq / (norm * (1.f + sq));

    float4 v = make_float4(factor * acc.x, factor * acc.y, factor * acc.z, factor * acc.w);
    if (LAST) {
        ((float4*)out)[(size_t)(b * NJ + j) * 4 + q] = v;
    } else {
        float4* vp = (float4*)g_vsum + (b * NJ + j) * 4 + q;
        if (FIRST) {
            *vp = v;
        } else {
            float4 o = *vp;
            *vp = make_float4(o.x + v.x, o.y + v.y, o.z + v.z, o.w + v.w);
        }
    }
}

extern "C" void kernel_launch(void* const* d_in, const int* in_sizes, int n_in,
                              void* d_out, int out_size) {
    const float* u = (const float*)d_in[0];
    const float* W = (const float*)d_in[1];
    float* out = (float*)d_out;

    const int smem = SMEM_WORDS * 4;
    cudaFuncSetAttribute(sweep_kernel<true>,  cudaFuncAttributeMaxDynamicSharedMemorySize, smem);
    cudaFuncSetAttribute(sweep_kernel<false>, cudaFuncAttributeMaxDynamicSharedMemorySize, smem);

    dim3 grid(ISPLITS, B_ / BT);
    const int rblocks = (B_ * NJ * 4 + 255) / 256;  // 80
    const int pthreads = NCHUNK_TOTAL * G_ * NJ * 33;  // 380160
    const int pblocks = (pthreads + 255) / 256;

    prepack_kernel<<<pblocks, 256>>>(W);                      // launch 0
    sweep_kernel<true><<<grid, THREADS, smem>>>(u);           // launch 1
    reduce_kernel<true, false><<<rblocks, 256>>>(out);        // launch 2
    sweep_kernel<false><<<grid, THREADS, smem>>>(u);          // launch 3
    reduce_kernel<false, false><<<rblocks, 256>>>(out);       // launch 4
    sweep_kernel<false><<<grid, THREADS, smem>>>(u);          // launch 5  <- ncu -s 5
    reduce_kernel<false, true><<<rblocks, 256>>>(out);        // launch 6
}

// round 5
// speedup vs baseline: 1.5550x; 1.1342x over previous
#include <cuda_runtime.h>
#include <cstdint>

// DigitCaps dynamic routing, fused.
// b_t[i,j] = u_hat[b,i,j,:] . Vsum_t[b,j,:], Vsum_t = sum_{tau<t} v_tau
// W prepacked to [chunk][g][e][dpair][j] (conflict-free LDS.64),
// staged via ONE cp.async.bulk per chunk into a 3-slot smem ring.

#define B_      512
#define NI      1152
#define NJ      10
#define DI      8
#define DO      16

#define THREADS 512
#define BT      16       // batches per block (8 pairs)
#define G_      6        // i's per chunk
#define ISPLITS 8
#define ICHUNK  144      // NI / ISPLITS
#define NCHUNK  24       // ICHUNK / G_
#define NCHUNK_TOTAL (ISPLITS * NCHUNK)   // 192
#define NPART   ISPLITS  // 8 partials per (b,j)

// W smem layout per chunk: [g][e][k][j] ull (k = d-pair)
#define WTILE_ULL  640                    // per i: 8e*8k*10j
#define WBUF_ULL   (G_ * WTILE_ULL)       // 3840 ull per ring slot
#define WBUF       (WBUF_ULL * 2)         // 7680 words
#define NBUF    3
#define VROW    18
#define CHUNK_BYTES (WBUF * 4)            // 30720
#define SMEM_WORDS (NBUF * WBUF + BT * NJ * VROW + 8)   // 23040+2880+8

__device__ float g_wpad[(size_t)NCHUNK_TOTAL * WBUF];      // 5.9 MB padded W image
__device__ float g_partial[(size_t)B_ * NPART * NJ * DO];
__device__ float g_vsum[B_ * NJ * DO];

using ull = unsigned long long;

__device__ __forceinline__ ull fma2(ull a, ull b, ull c) {
    ull d; asm("fma.rn.f32x2 %0, %1, %2, %3;" : "=l"(d) : "l"(a), "l"(b), "l"(c)); return d;
}
__device__ __forceinline__ ull bcast2(float x) {
    ull d; asm("mov.b64 %0, {%1, %1};" : "=l"(d) : "f"(x)); return d;
}
__device__ __forceinline__ ull pack2(float x, float y) {
    ull d; asm("mov.b64 %0, {%1, %2};" : "=l"(d) : "f"(x), "f"(y)); return d;
}
__device__ __forceinline__ float sum2(ull a) {
    float l, h; asm("mov.b64 {%0, %1}, %2;" : "=f"(l), "=f"(h) : "l"(a)); return l + h;
}
__device__ __forceinline__ void st2(float* p, ull v) { *(ull*)p = v; }

__device__ __forceinline__ void mbar_init(uint32_t addr, uint32_t count) {
    asm volatile("mbarrier.init.shared.b64 [%0], %1;" :: "r"(addr), "r"(count) : "memory");
}
__device__ __forceinline__ void mbar_wait(uint32_t addr, uint32_t parity) {
    asm volatile(
        "{\n\t.reg .pred P;\n\t"
        "WL_%=:\n\t"
        "mbarrier.try_wait.parity.acquire.cta.shared::cta.b64 P, [%0], %1, 0x989680;\n\t"
        "@P bra.uni WD_%=;\n\t"
        "bra.uni WL_%=;\n\t"
        "WD_%=:\n\t}"
        :: "r"(addr), "r"(parity) : "memory");
}

// ONE bulk copy per chunk: prepacked tile image -> ring slot.
__device__ __forceinline__ void issue_chunk(int chunk, int slot,
                                            uint32_t sbase, uint32_t mbase, int tid) {
    if (tid == 0) {
        uint32_t mbar = mbase + slot * 8;
        asm volatile("mbarrier.arrive.expect_tx.shared.b64 _, [%0], %1;"
                     :: "r"(mbar), "r"((uint32_t)CHUNK_BYTES) : "memory");
        const float* src = g_wpad + (size_t)chunk * WBUF;
        uint32_t dst = sbase + (uint32_t)(slot * WBUF) * 4;
        asm volatile(
            "cp.async.bulk.shared::cluster.global.mbarrier::complete_tx::bytes "
            "[%0], [%1], %2, [%3];"
            :: "r"(dst), "l"(src), "r"((uint32_t)CHUNK_BYTES), "r"(mbar) : "memory");
    }
}

// W[i][j][e][d] -> g_wpad ull[chunk*3840 + g*640 + e*80 + k*10 + j] = (W[..2k], W[..2k+1])
__global__ void prepack_kernel(const float* __restrict__ W) {
    int t = blockIdx.x * blockDim.x + threadIdx.x;   // one (i,j,e)
    if (t >= NI * NJ * DI) return;
    int e = t % DI;
    int r = t / DI;
    int j = r % NJ;
    int i = r / NJ;
    int chunk = i / G_;
    int g = i - chunk * G_;
    const float4* src = (const float4*)(W + (((size_t)(i * NJ + j)) * DI + e) * DO);
    float4 v0 = src[0], v1 = src[1], v2 = src[2], v3 = src[3];
    ull* dst = (ull*)g_wpad + (size_t)chunk * WBUF_ULL + g * WTILE_ULL + e * 80 + j;
    dst[0]  = pack2(v0.x, v0.y);
    dst[10] = pack2(v0.z, v0.w);
    dst[20] = pack2(v1.x, v1.y);
    dst[30] = pack2(v1.z, v1.w);
    dst[40] = pack2(v2.x, v2.y);
    dst[50] = pack2(v2.z, v2.w);
    dst[60] = pack2(v3.x, v3.y);
    dst[70] = pack2(v3.z, v3.w);
}

template <bool FIRST>
__global__ void __launch_bounds__(THREADS, 1)
sweep_kernel(const float* __restrict__ u) {
    extern __shared__ float smem[];
    float* wst = smem;                       // W ring, 3 slots
    float* vsm = smem + NBUF * WBUF;         // Vsum stage (padded rows)
    float* red = smem;                       // post-loop staging (reuses ring)

    const int tid  = threadIdx.x;
    const int lane = tid & 31;
    const int warp = tid >> 5;
    const int seg  = lane / 10;              // 0..2 active, 3 idle
    const bool active = (seg < 3);
    const int j    = lane - seg * 10;
    const int unit = warp * 3 + (active ? seg : 0);
    const int bp   = unit & 7;
    const int g    = unit >> 3;              // 0..5

    const int c0g   = blockIdx.x * NCHUNK;
    const int i0    = blockIdx.x * ICHUNK;
    const int bbase = blockIdx.y * BT;

    uint32_t smem_base = (uint32_t)__cvta_generic_to_shared(wst);
    uint32_t mbar_base = (uint32_t)__cvta_generic_to_shared(smem + NBUF * WBUF + BT * NJ * VROW);

    if (tid == 0) {
        mbar_init(mbar_base + 0, 1);
        mbar_init(mbar_base + 8, 1);
        mbar_init(mbar_base + 16, 1);
    }
    if (!FIRST) {
        for (int idx = tid; idx < BT * NJ * DO; idx += THREADS) {
            vsm[(idx >> 4) * VROW + (idx & 15)] = g_vsum[bbase * NJ * DO + idx];
        }
    }
    __syncthreads();

    issue_chunk(c0g, 0, smem_base, mbar_base, tid);
    issue_chunk(c0g + 1, 1, smem_base, mbar_base, tid);

    ull sacc0[8], sacc1[8];
    #pragma unroll
    for (int k = 0; k < 8; k++) { sacc0[k] = 0ULL; sacc1[k] = 0ULL; }

    const int b0 = bbase + bp * 2;
    const float* u0p = u + (size_t)b0 * NI * DI;
    const float* u1p = u0p + (size_t)NI * DI;
    const float* vs0 = vsm + (bp * 2 * NJ + j) * VROW;
    const float* vs1 = vs0 + NJ * VROW;

    for (int c = 0; c < NCHUNK; c++) {
        const int buf = c % NBUF;
        const int i = i0 + c * G_ + g;

        float ur0[8], ur1[8];
        if (active) {
            float4 ua = *(const float4*)(u0p + (size_t)i * DI);
            float4 ub = *(const float4*)(u0p + (size_t)i * DI + 4);
            float4 uc = *(const float4*)(u1p + (size_t)i * DI);
            float4 ud = *(const float4*)(u1p + (size_t)i * DI + 4);
            ur0[0]=ua.x; ur0[1]=ua.y; ur0[2]=ua.z; ur0[3]=ua.w;
            ur0[4]=ub.x; ur0[5]=ub.y; ur0[6]=ub.z; ur0[7]=ub.w;
            ur1[0]=uc.x; ur1[1]=uc.y; ur1[2]=uc.z; ur1[3]=uc.w;
            ur1[4]=ud.x; ur1[5]=ud.y; ur1[6]=ud.z; ur1[7]=ud.w;
        }

        __syncthreads();   // all warps done with chunk c-1 -> its slot is reusable
        if (c + 2 < NCHUNK)
            issue_chunk(c0g + c + 2, (c + 2) % NBUF, smem_base, mbar_base, tid);

        mbar_wait(mbar_base + buf * 8, (c / NBUF) & 1);

        if (active) {
            // transposed layout: ull index = e*80 + k*10 + j (within [g] tile)
            const ull* wt = (const ull*)(wst + buf * WBUF) + g * WTILE_ULL + j;

            if (FIRST) {
                #pragma unroll
                for (int e = 0; e < 8; e++) {
                    const ull* wte = wt + e * 80;
                    ull ue0 = bcast2(ur0[e]);
                    ull ue1 = bcast2(ur1[e]);
                    #pragma unroll
                    for (int k = 0; k < 8; k++) {
                        ull wv = wte[k * 10];
                        sacc0[k] = fma2(ue0, wv, sacc0[k]);
                        sacc1[k] = fma2(ue1, wv, sacc1[k]);
                    }
                }
            } else {
                ull a0[8], a1[8];
                #pragma unroll
                for (int k = 0; k < 8; k++) { a0[k] = 0ULL; a1[k] = 0ULL; }
                #pragma unroll
                for (int e = 0; e < 8; e++) {
                    const ull* wte = wt + e * 80;
                    ull ue0 = bcast2(ur0[e]);
                    ull ue1 = bcast2(ur1[e]);
                    #pragma unroll
                    for (int k = 0; k < 8; k++) {
                        ull wv = wte[k * 10];
                        a0[k] = fma2(ue0, wv, a0[k]);
                        a1[k] = fma2(ue1, wv, a1[k]);
                    }
                }

                ull d0 = 0ULL, d1 = 0ULL;
                #pragma unroll
                for (int k = 0; k < 8; k++) {
                    ull v0 = ((const ull*)vs0)[k];
                    ull v1 = ((const ull*)vs1)[k];
                    d0 = fma2(a0[k], v0, d0);
                    d1 = fma2(a1[k], v1, d1);
                }
                float l0 = sum2(d0), l1 = sum2(d1);
                float e0 = __expf(l0), e1 = __expf(l1);
                float t0 = 0.f, t1 = 0.f;
                const int base = seg * 10;
                #pragma unroll
                for (int jj = 0; jj < 10; jj++) {
                    t0 += __shfl_sync(0x3FFFFFFFu, e0, base + jj);
                    t1 += __shfl_sync(0x3FFFFFFFu, e1, base + jj);
                }
                ull c0 = bcast2(e0 / t0);
                ull c1 = bcast2(e1 / t1);
                #pragma unroll
                for (int k = 0; k < 8; k++) {
                    sacc0[k] = fma2(c0, a0[k], sacc0[k]);
                    sacc1[k] = fma2(c1, a1[k], sacc1[k]);
                }
            }
        }
    }

    // ---- in-block reduction over g ----
    __syncthreads();
    if (active) {
        int r0 = ((bp * 6 + g) * 2 + 0) * 10 + j;
        int r1 = r0 + 10;
        #pragma unroll
        for (int k = 0; k < 8; k++) {
            st2(red + r0 * 16 + 2 * k, sacc0[k]);
            st2(red + r1 * 16 + 2 * k, sacc1[k]);
        }
    }
    __syncthreads();

    #pragma unroll 1
    for (int idx = tid; idx < BT * NJ * DO; idx += THREADS) {
        int d  = idx & 15;
        int r  = idx >> 4;
        int jj = r % 10;
        int r2 = r / 10;
        int bb = r2 & 1;
        int bpp = r2 >> 1;
        float s = 0.f;
        #pragma unroll
        for (int gg = 0; gg < 6; gg++)
            s += red[(((bpp * 6 + gg) * 2 + bb) * 10 + jj) * 16 + d];
        if (FIRST) s *= 0.1f;
        int b = bbase + bpp * 2 + bb;
        g_partial[((size_t)(b * NPART + blockIdx.x) * NJ + jj) * DO + d] = s;
    }
}

template <bool FIRST, bool LAST>
__global__ void reduce_kernel(float* __restrict__ out) {
    int t = blockIdx.x * blockDim.x + threadIdx.x;
    if (t >= B_ * NJ * 4) return;
    int q = t & 3;
    int j = (t >> 2) % NJ;
    int b = t / (NJ * 4);

    const float4* src = (const float4*)g_partial + ((size_t)(b * NPART) * NJ + j) * 4 + q;
    float4 acc = make_float4(0.f, 0.f, 0.f, 0.f);
    #pragma unroll
    for (int p = 0; p < NPART; p++) {
        float4 x = src[(size_t)p * NJ * 4];
        acc.x += x.x; acc.y += x.y; acc.z += x.z; acc.w += x.w;
    }

    float sq = acc.x * acc.x + acc.y * acc.y + acc.z * acc.z + acc.w * acc.w;
    sq += __shfl_xor_sync(0xFFFFFFFFu, sq, 1);
    sq += __shfl_xor_sync(0xFFFFFFFFu, sq, 2);
    float norm = sqrtf(sq);
    float factor = sq / (norm * (1.f + sq));

    float4 v = make_float4(factor * acc.x, factor * acc.y, factor * acc.z, factor * acc.w);
    if (LAST) {
        ((float4*)out)[(size_t)(b * NJ + j) * 4 + q] = v;
    } else {
        float4* vp = (float4*)g_vsum + (b * NJ + j) * 4 + q;
        if (FIRST) {
            *vp = v;
        } else {
            float4 o = *vp;
            *vp = make_float4(o.x + v.x, o.y + v.y, o.z + v.z, o.w + v.w);
        }
    }
}

extern "C" void kernel_launch(void* const* d_in, const int* in_sizes, int n_in,
                              void* d_out, int out_size) {
    const float* u = (const float*)d_in[0];
    const float* W = (const float*)d_in[1];
    float* out = (float*)d_out;

    const int smem = SMEM_WORDS * 4;
    cudaFuncSetAttribute(sweep_kernel<true>,  cudaFuncAttributeMaxDynamicSharedMemorySize, smem);
    cudaFuncSetAttribute(sweep_kernel<false>, cudaFuncAttributeMaxDynamicSharedMemorySize, smem);

    dim3 grid(ISPLITS, B_ / BT);
    const int rblocks = (B_ * NJ * 4 + 255) / 256;           // 80
    const int pthreads = NI * NJ * DI;                       // 92160
    const int pblocks = (pthreads + 255) / 256;

    prepack_kernel<<<pblocks, 256>>>(W);                      // launch 0
    sweep_kernel<true><<<grid, THREADS, smem>>>(u);           // launch 1
    reduce_kernel<true, false><<<rblocks, 256>>>(out);        // launch 2
    sweep_kernel<false><<<grid, THREADS, smem>>>(u);          // launch 3
    reduce_kernel<false, false><<<rblocks, 256>>>(out);       // launch 4
    sweep_kernel<false><<<grid, THREADS, smem>>>(u);          // launch 5  <- ncu -s 5
    reduce_kernel<false, true><<<rblocks, 256>>>(out);        // launch 6
}